// round 1
// baseline (speedup 1.0000x reference)
#include <cuda_runtime.h>
#include <cstdint>

#define NODES 100000
#define DIM 256
#define BATCH 4096
#define NF1 25
#define NF2 10

// Scratch (device globals: allocation is forbidden in kernel_launch)
__device__ float g_R[(size_t)NODES * 512];   // [node][0:256]=emb@Wa^T, [256:512]=emb@Wb^T  (~205 MB)
__device__ float g_Wcat[512 * 256];          // repacked W1 as [512 out, 256 in]
__device__ float g_C[BATCH * 512];           // [h0 | h1mean]
__device__ float g_E[BATCH * 256];           // layer-2 output

typedef unsigned long long u64;

__device__ __forceinline__ u64 ffma2(u64 a, u64 b, u64 c) {
    u64 d;
    asm("fma.rn.f32x2 %0, %1, %2, %3;" : "=l"(d) : "l"(a), "l"(b), "l"(c));
    return d;
}
__device__ __forceinline__ u64 pack2(float lo, float hi) {
    u64 d;
    asm("mov.b64 %0, {%1, %2};" : "=l"(d) : "r"(__float_as_uint(lo)), "r"(__float_as_uint(hi)));
    return d;
}
__device__ __forceinline__ void unpack2(u64 v, float& lo, float& hi) {
    unsigned a, b;
    asm("mov.b64 {%0, %1}, %2;" : "=r"(a), "=r"(b) : "l"(v));
    lo = __uint_as_float(a);
    hi = __uint_as_float(b);
}

// Repack W1[256,512] into Wcat[512,256]: rows 0:256 = Wa (W1[:, :256]), rows 256:512 = Wb (W1[:, 256:]).
__global__ void repack_w1(const float* __restrict__ W1) {
    int i = blockIdx.x * 256 + threadIdx.x;
    if (i < 512 * 256) {
        int n = i >> 8;
        int k = i & 255;
        g_Wcat[i] = (n < 256) ? W1[n * 512 + k] : W1[(n - 256) * 512 + 256 + k];
    }
}

// C[M,N] = A[M,K] @ Bm[N,K]^T  (Bm row-major [out,in]), optional relu.
// Tiles 128x128x16, 256 threads, 8x8 microtile, packed f32x2 FMA inner loop.
template <bool RELU>
__global__ __launch_bounds__(256) void sgemm_bt(
    const float* __restrict__ A, const float* __restrict__ Bm, float* __restrict__ Cm,
    int M, int N, int K)
{
    __shared__ float As[16][128];
    __shared__ float Bs[16][128];
    int tid = threadIdx.x;
    int tx = tid & 15;         // col group
    int ty = tid >> 4;         // row group
    int m0 = blockIdx.y * 128;
    int n0 = blockIdx.x * 128;

    u64 acc[8][4];
#pragma unroll
    for (int i = 0; i < 8; i++)
#pragma unroll
        for (int j = 0; j < 4; j++) acc[i][j] = 0ull;

    for (int k0 = 0; k0 < K; k0 += 16) {
        // Load A tile (transposed into smem): 128 rows x 16 cols
#pragma unroll
        for (int l = 0; l < 2; l++) {
            int f = tid * 2 + l;        // 0..511 float4 slots
            int row = f >> 2;
            int c4 = f & 3;
            float4 v = make_float4(0.f, 0.f, 0.f, 0.f);
            int r = m0 + row;
            if (r < M) v = *(const float4*)(A + (size_t)r * K + k0 + c4 * 4);
            As[c4 * 4 + 0][row] = v.x;
            As[c4 * 4 + 1][row] = v.y;
            As[c4 * 4 + 2][row] = v.z;
            As[c4 * 4 + 3][row] = v.w;
        }
        // Load B tile (transposed): 128 rows(N) x 16 cols(K)
#pragma unroll
        for (int l = 0; l < 2; l++) {
            int f = tid * 2 + l;
            int row = f >> 2;
            int c4 = f & 3;
            float4 v = make_float4(0.f, 0.f, 0.f, 0.f);
            int r = n0 + row;
            if (r < N) v = *(const float4*)(Bm + (size_t)r * K + k0 + c4 * 4);
            Bs[c4 * 4 + 0][row] = v.x;
            Bs[c4 * 4 + 1][row] = v.y;
            Bs[c4 * 4 + 2][row] = v.z;
            Bs[c4 * 4 + 3][row] = v.w;
        }
        __syncthreads();

#pragma unroll
        for (int kk = 0; kk < 16; kk++) {
            float4 a0 = *(const float4*)&As[kk][ty * 8];
            float4 a1 = *(const float4*)&As[kk][ty * 8 + 4];
            float4 b0 = *(const float4*)&Bs[kk][tx * 8];
            float4 b1 = *(const float4*)&Bs[kk][tx * 8 + 4];
            u64 bp0 = pack2(b0.x, b0.y);
            u64 bp1 = pack2(b0.z, b0.w);
            u64 bp2 = pack2(b1.x, b1.y);
            u64 bp3 = pack2(b1.z, b1.w);
            float av[8] = {a0.x, a0.y, a0.z, a0.w, a1.x, a1.y, a1.z, a1.w};
#pragma unroll
            for (int i = 0; i < 8; i++) {
                u64 ad = pack2(av[i], av[i]);
                acc[i][0] = ffma2(ad, bp0, acc[i][0]);
                acc[i][1] = ffma2(ad, bp1, acc[i][1]);
                acc[i][2] = ffma2(ad, bp2, acc[i][2]);
                acc[i][3] = ffma2(ad, bp3, acc[i][3]);
            }
        }
        __syncthreads();
    }

    // Store (N is always a multiple of 8 here, so the 8-col microtile never straddles N)
    if (n0 + tx * 8 < N) {
#pragma unroll
        for (int i = 0; i < 8; i++) {
            int m = m0 + ty * 8 + i;
            if (m < M) {
                float out[8];
#pragma unroll
                for (int j = 0; j < 4; j++) {
                    float lo, hi;
                    unpack2(acc[i][j], lo, hi);
                    if (RELU) { lo = fmaxf(lo, 0.f); hi = fmaxf(hi, 0.f); }
                    out[j * 2] = lo;
                    out[j * 2 + 1] = hi;
                }
                float4* dst = (float4*)(Cm + (size_t)m * N + n0 + tx * 8);
                dst[0] = make_float4(out[0], out[1], out[2], out[3]);
                dst[1] = make_float4(out[4], out[5], out[6], out[7]);
            }
        }
    }
}

// Per-batch-row gather + reduce on projected rows.
// h0[b]  = relu( Q[T0[b]] + (1/25) * sum_f P[T1[b,f]] )
// h1m[b] = (1/25) * sum_f relu( Q[T1[b,f]] + (1/10) * sum_j P[T2[(b*25+f),j]] )
// where Q = R[:, 0:256], P = R[:, 256:512].
__global__ __launch_bounds__(256) void gather_kernel(
    const int* __restrict__ T0, const int* __restrict__ T1, const int* __restrict__ T2)
{
    __shared__ int sT1[NF1];
    __shared__ int sT2[NF1 * NF2];
    int b = blockIdx.x;
    int c = threadIdx.x;
    if (c < NF1) sT1[c] = T1[b * NF1 + c];
    if (c < NF1 * NF2) sT2[c] = T2[b * NF1 * NF2 + c];
    __syncthreads();

    const float* __restrict__ R = g_R;

    // h0
    int t0 = T0[b];
    float q0 = R[t0 * 512 + c];
    float accP = 0.f;
#pragma unroll
    for (int f = 0; f < NF1; f++) accP += R[sT1[f] * 512 + 256 + c];
    g_C[b * 512 + c] = fmaxf(fmaf(accP, 1.f / 25.f, q0), 0.f);

    // h1 mean
    float acc = 0.f;
#pragma unroll 1
    for (int f = 0; f < NF1; f++) {
        float v = R[sT1[f] * 512 + c];
        float s = 0.f;
#pragma unroll
        for (int j = 0; j < NF2; j++) s += R[sT2[f * NF2 + j] * 512 + 256 + c];
        acc += fmaxf(fmaf(s, 1.f / 10.f, v), 0.f);
    }
    g_C[b * 512 + 256 + c] = acc * (1.f / 25.f);
}

extern "C" void kernel_launch(void* const* d_in, const int* in_sizes, int n_in,
                              void* d_out, int out_size)
{
    const int* T0 = (const int*)d_in[0];
    const int* T1 = (const int*)d_in[1];
    const int* T2 = (const int*)d_in[2];
    const float* emb = (const float*)d_in[3];
    const float* W2 = (const float*)d_in[5];
    const float* W3 = (const float*)d_in[6];
    const float* W1 = (const float*)d_in[4];
    float* out = (float*)d_out;

    void *pR, *pWcat, *pC, *pE;
    cudaGetSymbolAddress(&pR, g_R);
    cudaGetSymbolAddress(&pWcat, g_Wcat);
    cudaGetSymbolAddress(&pC, g_C);
    cudaGetSymbolAddress(&pE, g_E);

    // 1) Repack W1 -> Wcat[512,256]
    repack_w1<<<512, 256>>>(W1);

    // 2) R = emb @ Wcat^T : [100000, 512], K=256
    {
        dim3 grid(512 / 128, (NODES + 127) / 128);
        sgemm_bt<false><<<grid, 256>>>(emb, (const float*)pWcat, (float*)pR, NODES, 512, 256);
    }

    // 3) Gather + reduce -> g_C [4096, 512]
    gather_kernel<<<BATCH, 256>>>(T0, T1, T2);

    // 4) E = relu(C @ W2^T) : [4096, 256], K=512
    {
        dim3 grid(256 / 128, BATCH / 128);
        sgemm_bt<true><<<grid, 256>>>((const float*)pC, W2, (float*)pE, BATCH, 256, 512);
    }

    // 5) scores = E @ W3^T : [4096, 64], K=256
    {
        dim3 grid(1, BATCH / 128);
        sgemm_bt<false><<<grid, 256>>>((const float*)pE, W3, out, BATCH, 64, 256);
    }
}

// round 3
// speedup vs baseline: 2.3467x; 2.3467x over previous
#include <cuda_runtime.h>
#include <cstdint>

#define NODES 100000
#define BATCH 4096
#define NF1 25
#define NF2 10

// ---------------- device scratch (no runtime alloc allowed) ----------------
__device__ float g_R[(size_t)NODES * 512];   // projected rows [node][Q(256)|P(256)]
__device__ float g_Wcat[512 * 256];          // repacked W1 as [512 out, 256 in]
__device__ float g_C[BATCH * 512];           // [h0 | h1mean]
__device__ float g_E[BATCH * 256];           // layer-2 output

// ---------------- PTX helpers (sm_100 base target: NO tcgen05) ----------------
__device__ __forceinline__ uint32_t smem_u32(const void* p) {
    uint32_t a; asm("{ .reg .u64 t; cvta.to.shared.u64 t, %1; cvt.u32.u64 %0, t; }" : "=r"(a) : "l"(p));
    return a;
}
__device__ __forceinline__ void cp_async16(uint32_t dst, const void* src) {
    asm volatile("cp.async.cg.shared.global [%0], [%1], 16;" :: "r"(dst), "l"(src));
}
__device__ __forceinline__ void cp_commit() { asm volatile("cp.async.commit_group;" ::: "memory"); }
template <int N>
__device__ __forceinline__ void cp_wait() { asm volatile("cp.async.wait_group %0;" :: "n"(N) : "memory"); }

__device__ __forceinline__ uint32_t cvt_tf32(float f) {
    uint32_t u; asm("cvt.rna.tf32.f32 %0, %1;" : "=r"(u) : "f"(f)); return u;
}
__device__ __forceinline__ void mma_tf32(float* d, const uint32_t* a, const uint32_t* b) {
    asm volatile("mma.sync.aligned.m16n8k8.row.col.f32.tf32.tf32.f32 "
        "{%0,%1,%2,%3},{%4,%5,%6,%7},{%8,%9},{%0,%1,%2,%3};"
        : "+f"(d[0]), "+f"(d[1]), "+f"(d[2]), "+f"(d[3])
        : "r"(a[0]), "r"(a[1]), "r"(a[2]), "r"(a[3]), "r"(b[0]), "r"(b[1]));
}

// ---------------- W1 repack: [256,512] -> Wcat[512,256] ----------------
__global__ void repack_w1(const float* __restrict__ W1) {
    int i = blockIdx.x * 256 + threadIdx.x;
    if (i < 512 * 256) {
        int n = i >> 8;
        int k = i & 255;
        g_Wcat[i] = (n < 256) ? W1[n * 512 + k] : W1[(n - 256) * 512 + 256 + k];
    }
}

// ---------------- tf32 tensor-core GEMM: C[M,N] = A[M,K] @ Bm[N,K]^T ----------------
// CTA tile 128x128, k-chunk 32, double-buffered cp.async, 8 warps of 64(M)x32(N).
// smem rows padded to 36 floats -> conflict-free fragment loads.
// Requires K % 32 == 0. Handles ragged M and N < 128 via clamp/predication.
template <bool RELU>
__global__ __launch_bounds__(256, 2) void tf32_gemm_bt(
    const float* __restrict__ A, const float* __restrict__ Bm, float* __restrict__ Cm,
    int M, int N, int K)
{
    extern __shared__ float sm[];               // [A s0 | A s1 | B s0 | B s1], 4608 floats each
    const int tid = threadIdx.x;
    const int lane = tid & 31, wid = tid >> 5;
    const int wm = wid & 1, wn = wid >> 1;      // 2 x 4 warp grid
    const int qr = lane >> 2, qc = lane & 3;
    const int m0 = blockIdx.y * 128, n0 = blockIdx.x * 128;

    float acc[4][4][4];
#pragma unroll
    for (int mt = 0; mt < 4; mt++)
#pragma unroll
        for (int nt = 0; nt < 4; nt++)
#pragma unroll
            for (int r = 0; r < 4; r++) acc[mt][nt][r] = 0.f;

    const uint32_t smA = smem_u32(sm);
    const uint32_t smB = smA + 2 * 18432;
    const int NKC = K >> 5;

    // --- stage loader: 128 rows x 32 floats for A and B ---
    auto load_tile = [&](int c, int s) {
        const int k0 = c * 32;
        const uint32_t aBase = smA + s * 18432;
        const uint32_t bBase = smB + s * 18432;
#pragma unroll
        for (int i = 0; i < 4; i++) {
            int idx = tid + i * 256;
            int row = idx >> 3, seg = idx & 7;
            int m = m0 + row; if (m > M - 1) m = M - 1;
            cp_async16(aBase + row * 144 + seg * 16, A + (size_t)m * K + k0 + seg * 4);
            int n = n0 + row; if (n > N - 1) n = N - 1;
            cp_async16(bBase + row * 144 + seg * 16, Bm + (size_t)n * K + k0 + seg * 4);
        }
        cp_commit();
    };

    load_tile(0, 0);

    for (int c = 0; c < NKC; ++c) {
        const int s = c & 1;
        if (c + 1 < NKC) { load_tile(c + 1, s ^ 1); cp_wait<1>(); }
        else cp_wait<0>();
        __syncthreads();

        const float* As = sm + s * 4608;
        const float* Bs = sm + 9216 + s * 4608;
#pragma unroll
        for (int kk = 0; kk < 4; kk++) {
            uint32_t af[4][4], bf[4][2];
#pragma unroll
            for (int mt = 0; mt < 4; mt++) {
                const float* p = As + (wm * 64 + mt * 16 + qr) * 36 + kk * 8 + qc;
                af[mt][0] = cvt_tf32(p[0]);
                af[mt][1] = cvt_tf32(p[8 * 36]);
                af[mt][2] = cvt_tf32(p[4]);
                af[mt][3] = cvt_tf32(p[8 * 36 + 4]);
            }
#pragma unroll
            for (int nt = 0; nt < 4; nt++) {
                const float* p = Bs + (wn * 32 + nt * 8 + qr) * 36 + kk * 8 + qc;
                bf[nt][0] = cvt_tf32(p[0]);
                bf[nt][1] = cvt_tf32(p[4]);
            }
#pragma unroll
            for (int mt = 0; mt < 4; mt++)
#pragma unroll
                for (int nt = 0; nt < 4; nt++)
                    mma_tf32(acc[mt][nt], af[mt], bf[nt]);
        }
        __syncthreads();
    }

    // --- epilogue: direct float2 stores ---
#pragma unroll
    for (int mt = 0; mt < 4; mt++) {
#pragma unroll
        for (int nt = 0; nt < 4; nt++) {
            int rg = m0 + wm * 64 + mt * 16 + qr;
            int cg = n0 + wn * 32 + nt * 8 + qc * 2;
            if (cg < N) {
                float v0 = acc[mt][nt][0], v1 = acc[mt][nt][1];
                float v2 = acc[mt][nt][2], v3 = acc[mt][nt][3];
                if (RELU) {
                    v0 = fmaxf(v0, 0.f); v1 = fmaxf(v1, 0.f);
                    v2 = fmaxf(v2, 0.f); v3 = fmaxf(v3, 0.f);
                }
                if (rg < M)     *(float2*)(Cm + (size_t)rg * N + cg)       = make_float2(v0, v1);
                if (rg + 8 < M) *(float2*)(Cm + (size_t)(rg + 8) * N + cg) = make_float2(v2, v3);
            }
        }
    }
}

// ---------------- gather + reduce on projected rows ----------------
// h0[b]  = relu( Q[T0[b]] + (1/25) * sum_f P[T1[b,f]] )
// h1m[b] = (1/25) * sum_f relu( Q[T1[b,f]] + (1/10) * sum_j P[T2[(b*25+f),j]] )
__global__ __launch_bounds__(256) void gather_kernel(
    const int* __restrict__ T0, const int* __restrict__ T1, const int* __restrict__ T2)
{
    __shared__ int sT1[NF1];
    __shared__ int sT2[NF1 * NF2];
    int b = blockIdx.x;
    int c = threadIdx.x;
    if (c < NF1) sT1[c] = T1[b * NF1 + c];
    if (c < NF1 * NF2) sT2[c] = T2[b * NF1 * NF2 + c];
    __syncthreads();

    const float* __restrict__ R = g_R;
    int t0 = T0[b];
    float q0 = R[(size_t)t0 * 512 + c];
    float accP = 0.f;
#pragma unroll
    for (int f = 0; f < NF1; f++) accP += R[(size_t)sT1[f] * 512 + 256 + c];
    g_C[b * 512 + c] = fmaxf(fmaf(accP, 1.f / 25.f, q0), 0.f);

    float acc = 0.f;
#pragma unroll 1
    for (int f = 0; f < NF1; f++) {
        float v = R[(size_t)sT1[f] * 512 + c];
        float s = 0.f;
#pragma unroll
        for (int j = 0; j < NF2; j++) s += R[(size_t)sT2[f * NF2 + j] * 512 + 256 + c];
        acc += fmaxf(fmaf(s, 1.f / 10.f, v), 0.f);
    }
    g_C[b * 512 + 256 + c] = acc * (1.f / 25.f);
}

// ---------------- launch ----------------
static constexpr int GEMM_SMEM = 4 * 18432;   // 73728 B

extern "C" void kernel_launch(void* const* d_in, const int* in_sizes, int n_in,
                              void* d_out, int out_size)
{
    const int* T0 = (const int*)d_in[0];
    const int* T1 = (const int*)d_in[1];
    const int* T2 = (const int*)d_in[2];
    const float* emb = (const float*)d_in[3];
    const float* W1 = (const float*)d_in[4];
    const float* W2 = (const float*)d_in[5];
    const float* W3 = (const float*)d_in[6];
    float* out = (float*)d_out;

    void *pR, *pW, *pC, *pE;
    cudaGetSymbolAddress(&pR, g_R);
    cudaGetSymbolAddress(&pW, g_Wcat);
    cudaGetSymbolAddress(&pC, g_C);
    cudaGetSymbolAddress(&pE, g_E);

    cudaFuncSetAttribute(tf32_gemm_bt<false>, cudaFuncAttributeMaxDynamicSharedMemorySize, GEMM_SMEM);
    cudaFuncSetAttribute(tf32_gemm_bt<true>,  cudaFuncAttributeMaxDynamicSharedMemorySize, GEMM_SMEM);

    // 1) repack W1
    repack_w1<<<512, 256>>>(W1);

    // 2) R = emb @ Wcat^T : [100000, 512], K=256  (tf32 tensor cores)
    {
        dim3 grid(512 / 128, (NODES + 127) / 128);
        tf32_gemm_bt<false><<<grid, 256, GEMM_SMEM>>>(emb, (const float*)pW, (float*)pR, NODES, 512, 256);
    }

    // 3) gather + reduce -> g_C [4096, 512]
    gather_kernel<<<BATCH, 256>>>(T0, T1, T2);

    // 4) E = relu(C @ W2^T) : [4096, 256], K=512
    {
        dim3 grid(256 / 128, BATCH / 128);
        tf32_gemm_bt<true><<<grid, 256, GEMM_SMEM>>>((const float*)pC, W2, (float*)pE, BATCH, 256, 512);
    }

    // 5) scores = E @ W3^T : [4096, 64], K=256
    {
        dim3 grid(1, BATCH / 128);
        tf32_gemm_bt<false><<<grid, 256, GEMM_SMEM>>>((const float*)pE, W3, out, BATCH, 64, 256);
    }
}

// round 4
// speedup vs baseline: 2.6689x; 1.1373x over previous
#include <cuda_runtime.h>
#include <cuda_fp16.h>
#include <cstdint>

#define NODES 100000
#define BATCH 4096
#define NF1 25
#define NF2 10

// ---------------- device scratch ----------------
__device__ float  g_A32[(size_t)NODES * 256];   // emb pre-rounded to tf32 bit patterns
__device__ float  g_RQ[(size_t)NODES * 256];    // R Q-half fp32
__device__ __half g_RP[(size_t)NODES * 256];    // R P-half fp16
__device__ float  g_Wcat[512 * 256];            // [Wa;Wb] rounded
__device__ float  g_W2r[256 * 512];             // W2 rounded
__device__ float  g_W3r[64 * 256];              // W3 rounded
__device__ float  g_C[BATCH * 512];             // [h0 | h1mean], tf32-rounded
__device__ float  g_E[BATCH * 256];             // layer-2 out, tf32-rounded

// ---------------- PTX helpers ----------------
__device__ __forceinline__ uint32_t smem_u32(const void* p) {
    uint32_t a; asm("{ .reg .u64 t; cvta.to.shared.u64 t, %1; cvt.u32.u64 %0, t; }" : "=r"(a) : "l"(p));
    return a;
}
__device__ __forceinline__ void cp_async16(uint32_t dst, const void* src) {
    asm volatile("cp.async.cg.shared.global [%0], [%1], 16;" :: "r"(dst), "l"(src));
}
__device__ __forceinline__ void cp_commit() { asm volatile("cp.async.commit_group;" ::: "memory"); }
template <int N>
__device__ __forceinline__ void cp_wait() { asm volatile("cp.async.wait_group %0;" :: "n"(N) : "memory"); }

__device__ __forceinline__ uint32_t cvt_tf32(float f) {
    uint32_t u; asm("cvt.rna.tf32.f32 %0, %1;" : "=r"(u) : "f"(f)); return u;
}
__device__ __forceinline__ float round_tf32(float f) { return __uint_as_float(cvt_tf32(f)); }

__device__ __forceinline__ void mma_tf32(float* d, const uint32_t* a, const uint32_t* b) {
    asm volatile("mma.sync.aligned.m16n8k8.row.col.f32.tf32.tf32.f32 "
        "{%0,%1,%2,%3},{%4,%5,%6,%7},{%8,%9},{%0,%1,%2,%3};"
        : "+f"(d[0]), "+f"(d[1]), "+f"(d[2]), "+f"(d[3])
        : "r"(a[0]), "r"(a[1]), "r"(a[2]), "r"(a[3]), "r"(b[0]), "r"(b[1]));
}

// ---------------- conversion kernels ----------------
// Wcat (131072) + W2r (131072) + W3r (16384) = 278528 elems
__global__ __launch_bounds__(256) void conv_w(const float* __restrict__ W1,
                                              const float* __restrict__ W2,
                                              const float* __restrict__ W3) {
    int idx = blockIdx.x * 256 + threadIdx.x;
    if (idx < 131072) {
        int n = idx >> 8, k = idx & 255;
        float w = (n < 256) ? W1[n * 512 + k] : W1[(n - 256) * 512 + 256 + k];
        g_Wcat[idx] = round_tf32(w);
    } else if (idx < 262144) {
        int j = idx - 131072;
        g_W2r[j] = round_tf32(W2[j]);
    } else if (idx < 278528) {
        int j = idx - 262144;
        g_W3r[j] = round_tf32(W3[j]);
    }
}

__global__ __launch_bounds__(256) void conv_emb(const float* __restrict__ emb) {
    int i4 = blockIdx.x * 256 + threadIdx.x;     // float4 index, exactly NODES*64
    float4 v = ((const float4*)emb)[i4];
    v.x = round_tf32(v.x); v.y = round_tf32(v.y);
    v.z = round_tf32(v.z); v.w = round_tf32(v.w);
    ((float4*)g_A32)[i4] = v;
}

// ---------------- tf32 tensor-core GEMM (pre-rounded inputs, no inner cvt) ----------------
// C = A[M,K] @ Bm[N,K]^T. CTA tile TM x 128, k-chunk 32, cp.async double buffer.
// 8 warps, warp tile (TM/2) x 32. Output split: cols < s0 -> C0 (fp32, row stride s0),
// cols >= s0 -> C1h (fp16, row stride N-s0) when SPLIT_HALF.
template <int TM, bool RELU, bool ROUND_OUT, bool SPLIT_HALF>
__global__ __launch_bounds__(256, 2) void tf32_gemm(
    const float* __restrict__ A, const float* __restrict__ Bm,
    float* __restrict__ C0, __half* __restrict__ C1h, int s0,
    int M, int N, int K)
{
    constexpr int MT  = TM / 32;          // m-subtiles per warp
    constexpr int ASZ = TM * 36;          // floats per A stage
    constexpr int BSZ = 128 * 36;
    extern __shared__ float sm[];
    const int tid = threadIdx.x;
    const int lane = tid & 31, wid = tid >> 5;
    const int wm = wid & 1, wn = wid >> 1;
    const int qr = lane >> 2, qc = lane & 3;
    const int m0 = blockIdx.y * TM, n0 = blockIdx.x * 128;

    float acc[MT][4][4];
#pragma unroll
    for (int mt = 0; mt < MT; mt++)
#pragma unroll
        for (int nt = 0; nt < 4; nt++)
#pragma unroll
            for (int r = 0; r < 4; r++) acc[mt][nt][r] = 0.f;

    const uint32_t smA = smem_u32(sm);
    const int NKC = K >> 5;

    auto load_tile = [&](int c, int s) {
        const int k0 = c * 32;
        const uint32_t aBase = smA + s * (ASZ * 4);
        const uint32_t bBase = smA + (2 * ASZ + s * BSZ) * 4;
#pragma unroll
        for (int i = 0; i < TM / 32; i++) {
            int idx = tid + i * 256;
            int row = idx >> 3, seg = idx & 7;
            int m = m0 + row; if (m > M - 1) m = M - 1;
            cp_async16(aBase + row * 144 + seg * 16, A + (size_t)m * K + k0 + seg * 4);
        }
#pragma unroll
        for (int i = 0; i < 4; i++) {
            int idx = tid + i * 256;
            int row = idx >> 3, seg = idx & 7;
            int n = n0 + row; if (n > N - 1) n = N - 1;
            cp_async16(bBase + row * 144 + seg * 16, Bm + (size_t)n * K + k0 + seg * 4);
        }
        cp_commit();
    };

    load_tile(0, 0);

    for (int c = 0; c < NKC; ++c) {
        const int s = c & 1;
        if (c + 1 < NKC) { load_tile(c + 1, s ^ 1); cp_wait<1>(); }
        else cp_wait<0>();
        __syncthreads();

        const float* As = sm + s * ASZ;
        const float* Bs = sm + 2 * ASZ + s * BSZ;
#pragma unroll
        for (int kk = 0; kk < 4; kk++) {
            uint32_t af[MT][4], bf[4][2];
#pragma unroll
            for (int mt = 0; mt < MT; mt++) {
                const float* p = As + (wm * (TM / 2) + mt * 16 + qr) * 36 + kk * 8 + qc;
                af[mt][0] = __float_as_uint(p[0]);
                af[mt][1] = __float_as_uint(p[8 * 36]);
                af[mt][2] = __float_as_uint(p[4]);
                af[mt][3] = __float_as_uint(p[8 * 36 + 4]);
            }
#pragma unroll
            for (int nt = 0; nt < 4; nt++) {
                const float* p = Bs + (wn * 32 + nt * 8 + qr) * 36 + kk * 8 + qc;
                bf[nt][0] = __float_as_uint(p[0]);
                bf[nt][1] = __float_as_uint(p[4]);
            }
#pragma unroll
            for (int mt = 0; mt < MT; mt++)
#pragma unroll
                for (int nt = 0; nt < 4; nt++)
                    mma_tf32(acc[mt][nt], af[mt], bf[nt]);
        }
        __syncthreads();
    }

    // epilogue
#pragma unroll
    for (int mt = 0; mt < MT; mt++) {
#pragma unroll
        for (int nt = 0; nt < 4; nt++) {
            int rg = m0 + wm * (TM / 2) + mt * 16 + qr;
            int cg = n0 + wn * 32 + nt * 8 + qc * 2;
            if (cg >= N) continue;
#pragma unroll
            for (int h = 0; h < 2; h++) {
                int r = rg + h * 8;
                if (r >= M) continue;
                float a = acc[mt][nt][h * 2], b = acc[mt][nt][h * 2 + 1];
                if (RELU) { a = fmaxf(a, 0.f); b = fmaxf(b, 0.f); }
                if (SPLIT_HALF && cg >= s0) {
                    *(__half2*)(C1h + (size_t)r * (N - s0) + (cg - s0)) = __floats2half2_rn(a, b);
                } else {
                    if (ROUND_OUT) { a = round_tf32(a); b = round_tf32(b); }
                    *(float2*)(C0 + (size_t)r * s0 + cg) = make_float2(a, b);
                }
            }
        }
    }
}

// ---------------- gather + reduce (128 threads, float2/half2 lanes) ----------------
__global__ __launch_bounds__(128) void gather_kernel(
    const int* __restrict__ T0, const int* __restrict__ T1, const int* __restrict__ T2)
{
    __shared__ int sT1[NF1];
    __shared__ int sT2[NF1 * NF2];
    const int b = blockIdx.x;
    const int t = threadIdx.x;
    if (t < NF1) sT1[t] = T1[b * NF1 + t];
    for (int i = t; i < NF1 * NF2; i += 128) sT2[i] = T2[b * NF1 * NF2 + i];
    __syncthreads();

    const int c2 = t * 2;

    // h0 = relu( Q[T0] + mean_f P[T1_f] )
    int t0 = T0[b];
    float2 q0 = *(const float2*)&g_RQ[(size_t)t0 * 256 + c2];
    float p0 = 0.f, p1 = 0.f;
#pragma unroll
    for (int f = 0; f < NF1; f++) {
        float2 v = __half22float2(*(const __half2*)&g_RP[(size_t)sT1[f] * 256 + c2]);
        p0 += v.x; p1 += v.y;
    }
    float h0a = fmaxf(fmaf(p0, 1.f / 25.f, q0.x), 0.f);
    float h0b = fmaxf(fmaf(p1, 1.f / 25.f, q0.y), 0.f);
    *(float2*)&g_C[b * 512 + c2] = make_float2(round_tf32(h0a), round_tf32(h0b));

    // h1mean = mean_f relu( Q[T1_f] + mean_j P[T2_fj] )
    float a0 = 0.f, a1 = 0.f;
#pragma unroll 1
    for (int f = 0; f < NF1; f++) {
        float2 q = *(const float2*)&g_RQ[(size_t)sT1[f] * 256 + c2];
        float s0 = 0.f, s1 = 0.f;
#pragma unroll
        for (int j = 0; j < NF2; j++) {
            float2 v = __half22float2(*(const __half2*)&g_RP[(size_t)sT2[f * NF2 + j] * 256 + c2]);
            s0 += v.x; s1 += v.y;
        }
        a0 += fmaxf(fmaf(s0, 1.f / 10.f, q.x), 0.f);
        a1 += fmaxf(fmaf(s1, 1.f / 10.f, q.y), 0.f);
    }
    *(float2*)&g_C[b * 512 + 256 + c2] =
        make_float2(round_tf32(a0 * (1.f / 25.f)), round_tf32(a1 * (1.f / 25.f)));
}

// ---------------- launch ----------------
static constexpr int SM128 = 2 * (128 * 36 + 128 * 36) * 4;  // 73728
static constexpr int SM64  = 2 * (64 * 36 + 128 * 36) * 4;   // 55296

extern "C" void kernel_launch(void* const* d_in, const int* in_sizes, int n_in,
                              void* d_out, int out_size)
{
    const int* T0 = (const int*)d_in[0];
    const int* T1 = (const int*)d_in[1];
    const int* T2 = (const int*)d_in[2];
    const float* emb = (const float*)d_in[3];
    const float* W1 = (const float*)d_in[4];
    const float* W2 = (const float*)d_in[5];
    const float* W3 = (const float*)d_in[6];
    float* out = (float*)d_out;

    void *pA32, *pRQ, *pRP, *pW, *pW2, *pW3, *pC, *pE;
    cudaGetSymbolAddress(&pA32, g_A32);
    cudaGetSymbolAddress(&pRQ, g_RQ);
    cudaGetSymbolAddress(&pRP, g_RP);
    cudaGetSymbolAddress(&pW, g_Wcat);
    cudaGetSymbolAddress(&pW2, g_W2r);
    cudaGetSymbolAddress(&pW3, g_W3r);
    cudaGetSymbolAddress(&pC, g_C);
    cudaGetSymbolAddress(&pE, g_E);

    cudaFuncSetAttribute((const void*)tf32_gemm<128, false, false, true>,
                         cudaFuncAttributeMaxDynamicSharedMemorySize, SM128);
    cudaFuncSetAttribute((const void*)tf32_gemm<64, true, true, false>,
                         cudaFuncAttributeMaxDynamicSharedMemorySize, SM64);
    cudaFuncSetAttribute((const void*)tf32_gemm<64, false, false, false>,
                         cudaFuncAttributeMaxDynamicSharedMemorySize, SM64);

    // 1) round weights + emb to tf32
    conv_w<<<1088, 256>>>(W1, W2, W3);
    conv_emb<<<NODES * 64 / 256, 256>>>(emb);

    // 2) R = emb @ Wcat^T : [100000, 512]; cols 0:256 -> g_RQ fp32, 256:512 -> g_RP fp16
    {
        dim3 grid(4, (NODES + 127) / 128);
        tf32_gemm<128, false, false, true><<<grid, 256, SM128>>>(
            (const float*)pA32, (const float*)pW, (float*)pRQ, (__half*)pRP, 256, NODES, 512, 256);
    }

    // 3) gather + reduce -> g_C [4096, 512] (tf32-rounded)
    gather_kernel<<<BATCH, 128>>>(T0, T1, T2);

    // 4) E = relu(C @ W2^T) : [4096, 256], K=512, rounded for layer 3
    {
        dim3 grid(2, BATCH / 64);
        tf32_gemm<64, true, true, false><<<grid, 256, SM64>>>(
            (const float*)pC, (const float*)pW2, (float*)pE, nullptr, 256, BATCH, 256, 512);
    }

    // 5) scores = E @ W3^T : [4096, 64], K=256
    {
        dim3 grid(1, BATCH / 64);
        tf32_gemm<64, false, false, false><<<grid, 256, SM64>>>(
            (const float*)pE, (const float*)pW3, out, nullptr, 64, BATCH, 64, 256);
    }
}

// round 5
// speedup vs baseline: 3.0680x; 1.1496x over previous
#include <cuda_runtime.h>
#include <cuda_fp16.h>
#include <cstdint>

#define NODES 100000
#define BATCH 4096
#define NF1 25
#define NF2 10

// ---------------- device scratch ----------------
__device__ float  g_A32[(size_t)NODES * 256];   // emb: tf32-rounded, K-permuted
__device__ __half g_Rh[(size_t)NODES * 512];    // R rows: [Q(256) | P(256)] fp16
__device__ float  g_Wcat[512 * 256];            // [Wa;Wb] rounded, K-permuted
__device__ float  g_W2r[256 * 512];             // W2 rounded, K-permuted
__device__ float  g_W3r[64 * 256];              // W3 rounded, K-permuted
__device__ float  g_C[BATCH * 512];             // [h0|h1mean] rounded, K-permuted
__device__ float  g_E[BATCH * 256];             // layer-2 out rounded, K-permuted

// ---------------- PTX helpers ----------------
__device__ __forceinline__ uint32_t smem_u32(const void* p) {
    uint32_t a; asm("{ .reg .u64 t; cvta.to.shared.u64 t, %1; cvt.u32.u64 %0, t; }" : "=r"(a) : "l"(p));
    return a;
}
__device__ __forceinline__ void cp_async16(uint32_t dst, const void* src) {
    asm volatile("cp.async.cg.shared.global [%0], [%1], 16;" :: "r"(dst), "l"(src));
}
__device__ __forceinline__ void cp_commit() { asm volatile("cp.async.commit_group;" ::: "memory"); }
template <int N>
__device__ __forceinline__ void cp_wait() { asm volatile("cp.async.wait_group %0;" :: "n"(N) : "memory"); }

__device__ __forceinline__ uint32_t cvt_tf32(float f) {
    uint32_t u; asm("cvt.rna.tf32.f32 %0, %1;" : "=r"(u) : "f"(f)); return u;
}
__device__ __forceinline__ float round_tf32(float f) { return __uint_as_float(cvt_tf32(f)); }

__device__ __forceinline__ void mma_tf32(float* d, const uint32_t* a, const uint32_t* b) {
    asm volatile("mma.sync.aligned.m16n8k8.row.col.f32.tf32.tf32.f32 "
        "{%0,%1,%2,%3},{%4,%5,%6,%7},{%8,%9},{%0,%1,%2,%3};"
        : "+f"(d[0]), "+f"(d[1]), "+f"(d[2]), "+f"(d[3])
        : "r"(a[0]), "r"(a[1]), "r"(a[2]), "r"(a[3]), "r"(b[0]), "r"(b[1]));
}

// K-permutation: within each 8-col group, position p holds src col (p>>1)+(p&1)*4.
// forward: col c -> position 2*(c&3)+((c&7)>>2) within group.
__device__ __forceinline__ int permc(int c) { return (c & ~7) + 2 * (c & 3) + ((c & 7) >> 2); }

__device__ __forceinline__ float4 ldh4(const void* p) {
    uint2 u = *(const uint2*)p;
    float2 f0 = __half22float2(*(__half2*)&u.x);
    float2 f1 = __half22float2(*(__half2*)&u.y);
    return make_float4(f0.x, f0.y, f1.x, f1.y);
}

// ---------------- conversion kernels ----------------
// Round + permute all three weight matrices. dst index space: 131072 + 131072 + 16384.
__global__ __launch_bounds__(256) void conv_w(const float* __restrict__ W1,
                                              const float* __restrict__ W2,
                                              const float* __restrict__ W3) {
    int idx = blockIdx.x * 256 + threadIdx.x;
    if (idx < 131072) {              // Wcat[512,256] <- [Wa;Wb], K-permuted
        int n = idx >> 8, p = idx & 255;
        int c = (p & ~7) + ((p & 7) >> 1) + (p & 1) * 4;   // src col
        float w = (n < 256) ? W1[n * 512 + c] : W1[(n - 256) * 512 + 256 + c];
        g_Wcat[idx] = round_tf32(w);
    } else if (idx < 262144) {       // W2r[256,512] K-permuted
        int j = idx - 131072;
        int n = j >> 9, p = j & 511;
        int c = (p & ~7) + ((p & 7) >> 1) + (p & 1) * 4;
        g_W2r[j] = round_tf32(W2[n * 512 + c]);
    } else if (idx < 278528) {       // W3r[64,256] K-permuted
        int j = idx - 262144;
        int n = j >> 8, p = j & 255;
        int c = (p & ~7) + ((p & 7) >> 1) + (p & 1) * 4;
        g_W3r[j] = round_tf32(W3[n * 256 + c]);
    }
}

// emb -> g_A32: round to tf32 + permute each 8-col group. One thread = 8 floats.
__global__ __launch_bounds__(256) void conv_emb(const float* __restrict__ emb) {
    int i8 = blockIdx.x * 256 + threadIdx.x;     // group index, NODES*32 total
    const float4* s = (const float4*)emb + i8 * 2;
    float4 a = s[0], b = s[1];                   // src cols 0..3, 4..7
    float4 d0 = make_float4(round_tf32(a.x), round_tf32(b.x), round_tf32(a.y), round_tf32(b.y));
    float4 d1 = make_float4(round_tf32(a.z), round_tf32(b.z), round_tf32(a.w), round_tf32(b.w));
    float4* d = (float4*)g_A32 + i8 * 2;
    d[0] = d0; d[1] = d1;
}

// ---------------- tf32 GEMM: C = A[M,K] @ Bm[N,K]^T, K-permuted inputs ----------------
// CTA tile TM x 128, k-chunk 32 double-buffered, 8 warps of (TM/2) x 32.
// Rows padded to 40 floats -> conflict-free LDS.64 fragment loads.
// OUT_MODE: 0 = fp32 float2 (normal), 1 = fp32 scalar K-permuted + tf32-rounded, 2 = fp16 half2.
template <int TM, bool RELU, int OUT_MODE>
__global__ __launch_bounds__(256, 2) void tf32_gemm(
    const float* __restrict__ A, const float* __restrict__ Bm,
    float* __restrict__ C0, __half* __restrict__ Ch,
    int M, int N, int K)
{
    constexpr int MT  = TM / 32;
    constexpr int ASZ = TM * 40;
    constexpr int BSZ = 128 * 40;
    extern __shared__ float sm[];
    const int tid = threadIdx.x;
    const int lane = tid & 31, wid = tid >> 5;
    const int wm = wid & 1, wn = wid >> 1;
    const int qr = lane >> 2, qc = lane & 3;
    const int m0 = blockIdx.y * TM, n0 = blockIdx.x * 128;

    float acc[MT][4][4];
#pragma unroll
    for (int mt = 0; mt < MT; mt++)
#pragma unroll
        for (int nt = 0; nt < 4; nt++)
#pragma unroll
            for (int r = 0; r < 4; r++) acc[mt][nt][r] = 0.f;

    const uint32_t smA = smem_u32(sm);
    const int NKC = K >> 5;

    auto load_tile = [&](int c, int s) {
        const int k0 = c * 32;
        const uint32_t aBase = smA + s * (ASZ * 4);
        const uint32_t bBase = smA + (2 * ASZ + s * BSZ) * 4;
#pragma unroll
        for (int i = 0; i < TM / 32; i++) {
            int idx = tid + i * 256;
            int row = idx >> 3, seg = idx & 7;
            int m = m0 + row; if (m > M - 1) m = M - 1;
            cp_async16(aBase + row * 160 + seg * 16, A + (size_t)m * K + k0 + seg * 4);
        }
#pragma unroll
        for (int i = 0; i < 4; i++) {
            int idx = tid + i * 256;
            int row = idx >> 3, seg = idx & 7;
            int n = n0 + row; if (n > N - 1) n = N - 1;
            cp_async16(bBase + row * 160 + seg * 16, Bm + (size_t)n * K + k0 + seg * 4);
        }
        cp_commit();
    };

    load_tile(0, 0);

    for (int c = 0; c < NKC; ++c) {
        const int s = c & 1;
        if (c + 1 < NKC) { load_tile(c + 1, s ^ 1); cp_wait<1>(); }
        else cp_wait<0>();
        __syncthreads();

        const float* As = sm + s * ASZ;
        const float* Bs = sm + 2 * ASZ + s * BSZ;
#pragma unroll
        for (int kk = 0; kk < 4; kk++) {
            uint32_t af[MT][4], bf[4][2];
#pragma unroll
            for (int mt = 0; mt < MT; mt++) {
                const float* p = As + (wm * (TM / 2) + mt * 16 + qr) * 40 + kk * 8 + 2 * qc;
                float2 v0 = *(const float2*)p;          // cols (qc, qc+4) @ row qr
                float2 v1 = *(const float2*)(p + 8 * 40); // @ row qr+8
                af[mt][0] = __float_as_uint(v0.x);
                af[mt][2] = __float_as_uint(v0.y);
                af[mt][1] = __float_as_uint(v1.x);
                af[mt][3] = __float_as_uint(v1.y);
            }
#pragma unroll
            for (int nt = 0; nt < 4; nt++) {
                const float* p = Bs + (wn * 32 + nt * 8 + qr) * 40 + kk * 8 + 2 * qc;
                float2 v = *(const float2*)p;
                bf[nt][0] = __float_as_uint(v.x);
                bf[nt][1] = __float_as_uint(v.y);
            }
#pragma unroll
            for (int mt = 0; mt < MT; mt++)
#pragma unroll
                for (int nt = 0; nt < 4; nt++)
                    mma_tf32(acc[mt][nt], af[mt], bf[nt]);
        }
        __syncthreads();
    }

    // epilogue
#pragma unroll
    for (int mt = 0; mt < MT; mt++) {
#pragma unroll
        for (int nt = 0; nt < 4; nt++) {
            int rg = m0 + wm * (TM / 2) + mt * 16 + qr;
            int cg = n0 + wn * 32 + nt * 8 + qc * 2;
            if (cg >= N) continue;
#pragma unroll
            for (int h = 0; h < 2; h++) {
                int r = rg + h * 8;
                if (r >= M) continue;
                float a = acc[mt][nt][h * 2], b = acc[mt][nt][h * 2 + 1];
                if (RELU) { a = fmaxf(a, 0.f); b = fmaxf(b, 0.f); }
                if (OUT_MODE == 2) {
                    *(__half2*)(Ch + (size_t)r * N + cg) = __floats2half2_rn(a, b);
                } else if (OUT_MODE == 1) {
                    C0[(size_t)r * N + permc(cg)]     = round_tf32(a);
                    C0[(size_t)r * N + permc(cg + 1)] = round_tf32(b);
                } else {
                    *(float2*)(C0 + (size_t)r * N + cg) = make_float2(a, b);
                }
            }
        }
    }
}

// ---------------- gather + reduce ----------------
// 128 threads: thread t -> colgroup (t&63)*4, f-half (t>>6). Row pointers precomputed in smem.
__global__ __launch_bounds__(128) void gather_kernel(
    const int* __restrict__ T0, const int* __restrict__ T1, const int* __restrict__ T2)
{
    __shared__ const char* sP1[NF1];
    __shared__ const char* sP2[NF1 * NF2];
    __shared__ float red[64 * 8];
    const int b = blockIdx.x;
    const int t = threadIdx.x;
    const char* Rb = (const char*)g_Rh;

    for (int i = t; i < NF1; i += 128)       sP1[i] = Rb + (size_t)T1[b * NF1 + i] * 1024;
    for (int i = t; i < NF1 * NF2; i += 128) sP2[i] = Rb + (size_t)T2[b * NF1 * NF2 + i] * 1024;
    __syncthreads();

    const int half = t >> 6;
    const int c4 = (t & 63) * 4;
    const int qoff = c4 * 2;          // bytes into Q region
    const int poff = 512 + c4 * 2;    // bytes into P region
    const int f0 = half ? 13 : 0, f1 = half ? NF1 : 13;

    // h0 partial: sum_f P[T1_f]
    float4 p = make_float4(0.f, 0.f, 0.f, 0.f);
    for (int f = f0; f < f1; f++) {
        float4 v = ldh4(sP1[f] + poff);
        p.x += v.x; p.y += v.y; p.z += v.z; p.w += v.w;
    }
    // h1 partial: sum_f relu(Q[T1_f] + mean_j P[T2_fj])
    float4 a = make_float4(0.f, 0.f, 0.f, 0.f);
#pragma unroll 1
    for (int f = f0; f < f1; f++) {
        float4 q = ldh4(sP1[f] + qoff);
        float4 s = make_float4(0.f, 0.f, 0.f, 0.f);
#pragma unroll
        for (int j = 0; j < NF2; j++) {
            float4 v = ldh4(sP2[f * NF2 + j] + poff);
            s.x += v.x; s.y += v.y; s.z += v.z; s.w += v.w;
        }
        a.x += fmaxf(fmaf(s.x, 0.1f, q.x), 0.f);
        a.y += fmaxf(fmaf(s.y, 0.1f, q.y), 0.f);
        a.z += fmaxf(fmaf(s.z, 0.1f, q.z), 0.f);
        a.w += fmaxf(fmaf(s.w, 0.1f, q.w), 0.f);
    }

    if (half == 1) {
        float* r = red + (t & 63) * 8;
        r[0] = p.x; r[1] = p.y; r[2] = p.z; r[3] = p.w;
        r[4] = a.x; r[5] = a.y; r[6] = a.z; r[7] = a.w;
    }
    __syncthreads();
    if (half == 0) {
        const float* r = red + c4 * 2;  // (t&63)*8
        p.x += r[0]; p.y += r[1]; p.z += r[2]; p.w += r[3];
        a.x += r[4]; a.y += r[5]; a.z += r[6]; a.w += r[7];
        const char* r0p = Rb + (size_t)T0[b] * 1024;
        float4 q0 = ldh4(r0p + qoff);
        float h0[4] = {
            fmaxf(fmaf(p.x, 1.f / 25.f, q0.x), 0.f),
            fmaxf(fmaf(p.y, 1.f / 25.f, q0.y), 0.f),
            fmaxf(fmaf(p.z, 1.f / 25.f, q0.z), 0.f),
            fmaxf(fmaf(p.w, 1.f / 25.f, q0.w), 0.f)};
        float h1[4] = {a.x * (1.f / 25.f), a.y * (1.f / 25.f), a.z * (1.f / 25.f), a.w * (1.f / 25.f)};
        float* Cr = g_C + b * 512;
#pragma unroll
        for (int i = 0; i < 4; i++) {
            Cr[permc(c4 + i)]       = round_tf32(h0[i]);
            Cr[256 + permc(c4 + i)] = round_tf32(h1[i]);
        }
    }
}

// ---------------- launch ----------------
static constexpr int SM128 = 2 * (128 * 40 + 128 * 40) * 4;  // 81920
static constexpr int SM64  = 2 * (64 * 40 + 128 * 40) * 4;   // 61440

extern "C" void kernel_launch(void* const* d_in, const int* in_sizes, int n_in,
                              void* d_out, int out_size)
{
    const int* T0 = (const int*)d_in[0];
    const int* T1 = (const int*)d_in[1];
    const int* T2 = (const int*)d_in[2];
    const float* emb = (const float*)d_in[3];
    const float* W1 = (const float*)d_in[4];
    const float* W2 = (const float*)d_in[5];
    const float* W3 = (const float*)d_in[6];
    float* out = (float*)d_out;

    void *pA32, *pRh, *pW, *pW2, *pW3, *pC, *pE;
    cudaGetSymbolAddress(&pA32, g_A32);
    cudaGetSymbolAddress(&pRh, g_Rh);
    cudaGetSymbolAddress(&pW, g_Wcat);
    cudaGetSymbolAddress(&pW2, g_W2r);
    cudaGetSymbolAddress(&pW3, g_W3r);
    cudaGetSymbolAddress(&pC, g_C);
    cudaGetSymbolAddress(&pE, g_E);

    cudaFuncSetAttribute((const void*)tf32_gemm<128, false, 2>,
                         cudaFuncAttributeMaxDynamicSharedMemorySize, SM128);
    cudaFuncSetAttribute((const void*)tf32_gemm<64, true, 1>,
                         cudaFuncAttributeMaxDynamicSharedMemorySize, SM64);
    cudaFuncSetAttribute((const void*)tf32_gemm<64, false, 0>,
                         cudaFuncAttributeMaxDynamicSharedMemorySize, SM64);

    // 1) round+permute weights and emb
    conv_w<<<1088, 256>>>(W1, W2, W3);
    conv_emb<<<NODES * 32 / 256, 256>>>(emb);

    // 2) R = emb @ Wcat^T : [100000, 512] -> g_Rh fp16
    {
        dim3 grid(4, (NODES + 127) / 128);
        tf32_gemm<128, false, 2><<<grid, 256, SM128>>>(
            (const float*)pA32, (const float*)pW, nullptr, (__half*)pRh, NODES, 512, 256);
    }

    // 3) gather + reduce -> g_C [4096, 512] (rounded, K-permuted)
    gather_kernel<<<BATCH, 128>>>(T0, T1, T2);

    // 4) E = relu(C @ W2^T) : [4096, 256], K=512 -> g_E (rounded, K-permuted)
    {
        dim3 grid(2, BATCH / 64);
        tf32_gemm<64, true, 1><<<grid, 256, SM64>>>(
            (const float*)pC, (const float*)pW2, (float*)pE, nullptr, BATCH, 256, 512);
    }

    // 5) scores = E @ W3^T : [4096, 64], K=256 -> out fp32
    {
        dim3 grid(1, BATCH / 64);
        tf32_gemm<64, false, 0><<<grid, 256, SM64>>>(
            (const float*)pE, (const float*)pW3, out, nullptr, BATCH, 64, 256);
    }
}

// round 8
// speedup vs baseline: 3.1093x; 1.0135x over previous
#include <cuda_runtime.h>
#include <cuda_fp16.h>
#include <cstdint>

#define NODES 100000
#define BATCH 4096
#define NF1 25
#define NF2 10

// ---------------- device scratch (16B-aligned: uint4/float4 access paths) ----------------
__device__ __align__(16) __half g_Rh[(size_t)NODES * 512];  // R rows: [Q(256) | P(256)] fp16
__device__ __align__(16) float  g_Wcat[512 * 256];          // [Wa;Wb] rounded, K-permuted
__device__ __align__(16) float  g_W2r[256 * 512];           // W2 rounded, K-permuted
__device__ __align__(16) float  g_W3r[64 * 256];            // W3 rounded, K-permuted
__device__ __align__(16) float  g_C[BATCH * 512];           // [h0|h1mean] rounded, K-permuted
__device__ __align__(16) float  g_E[BATCH * 256];           // layer-2 out rounded, K-permuted

// ---------------- PTX helpers ----------------
__device__ __forceinline__ uint32_t smem_u32(const void* p) {
    uint32_t a; asm("{ .reg .u64 t; cvta.to.shared.u64 t, %1; cvt.u32.u64 %0, t; }" : "=r"(a) : "l"(p));
    return a;
}
__device__ __forceinline__ void cp_async16(uint32_t dst, const void* src) {
    asm volatile("cp.async.cg.shared.global [%0], [%1], 16;" :: "r"(dst), "l"(src));
}
__device__ __forceinline__ void cp_commit() { asm volatile("cp.async.commit_group;" ::: "memory"); }
template <int N>
__device__ __forceinline__ void cp_wait() { asm volatile("cp.async.wait_group %0;" :: "n"(N) : "memory"); }

__device__ __forceinline__ uint32_t cvt_tf32(float f) {
    uint32_t u; asm("cvt.rna.tf32.f32 %0, %1;" : "=r"(u) : "f"(f)); return u;
}
__device__ __forceinline__ float round_tf32(float f) { return __uint_as_float(cvt_tf32(f)); }

__device__ __forceinline__ void mma_tf32(float* d, const uint32_t* a, const uint32_t* b) {
    asm volatile("mma.sync.aligned.m16n8k8.row.col.f32.tf32.tf32.f32 "
        "{%0,%1,%2,%3},{%4,%5,%6,%7},{%8,%9},{%0,%1,%2,%3};"
        : "+f"(d[0]), "+f"(d[1]), "+f"(d[2]), "+f"(d[3])
        : "r"(a[0]), "r"(a[1]), "r"(a[2]), "r"(a[3]), "r"(b[0]), "r"(b[1]));
}

// K-perm: src col c -> position 2*(c&3)+((c&7)>>2) within its 8-group.
__device__ __forceinline__ int permc(int c) { return (c & ~7) + 2 * (c & 3) + ((c & 7) >> 2); }

// ---------------- weight conversion ----------------
__global__ __launch_bounds__(256) void conv_w(const float* __restrict__ W1,
                                              const float* __restrict__ W2,
                                              const float* __restrict__ W3) {
    int idx = blockIdx.x * 256 + threadIdx.x;
    if (idx < 131072) {              // Wcat[512,256]
        int n = idx >> 8, p = idx & 255;
        int c = (p & ~7) + ((p & 7) >> 1) + (p & 1) * 4;
        float w = (n < 256) ? W1[n * 512 + c] : W1[(n - 256) * 512 + 256 + c];
        g_Wcat[idx] = round_tf32(w);
    } else if (idx < 262144) {       // W2r[256,512]
        int j = idx - 131072;
        int n = j >> 9, p = j & 511;
        int c = (p & ~7) + ((p & 7) >> 1) + (p & 1) * 4;
        g_W2r[j] = round_tf32(W2[n * 512 + c]);
    } else if (idx < 278528) {       // W3r[64,256]
        int j = idx - 262144;
        int n = j >> 8, p = j & 255;
        int c = (p & ~7) + ((p & 7) >> 1) + (p & 1) * 4;
        g_W3r[j] = round_tf32(W3[n * 256 + c]);
    }
}

// ---------------- tf32 GEMM: C = A[M,K] @ Bm[N,K]^T ----------------
// CTA TM x 128, k-chunk 32 double-buffered, 8 warps of (TM/2) x 32; rows padded to 40 floats.
// CONV_A: A is raw fp32 (unrounded, unpermuted); loader LDGs, rounds+permutes, STS.
// OUT_MODE: 0 = fp32 float2, 1 = fp32 scalar permuted+rounded, 2 = fp16 half2.
template <int TM, bool RELU, int OUT_MODE, bool CONV_A>
__global__ __launch_bounds__(256, 2) void tf32_gemm(
    const float* __restrict__ A, const float* __restrict__ Bm,
    float* __restrict__ C0, __half* __restrict__ Ch,
    int M, int N, int K)
{
    constexpr int MT  = TM / 32;
    constexpr int ASZ = TM * 40;
    constexpr int BSZ = 128 * 40;
    extern __shared__ float sm[];
    const int tid = threadIdx.x;
    const int lane = tid & 31, wid = tid >> 5;
    const int wm = wid & 1, wn = wid >> 1;
    const int qr = lane >> 2, qc = lane & 3;
    const int m0 = blockIdx.y * TM, n0 = blockIdx.x * 128;

    float acc[MT][4][4];
#pragma unroll
    for (int mt = 0; mt < MT; mt++)
#pragma unroll
        for (int nt = 0; nt < 4; nt++)
#pragma unroll
            for (int r = 0; r < 4; r++) acc[mt][nt][r] = 0.f;

    const uint32_t smA = smem_u32(sm);
    const int NKC = K >> 5;

    auto load_tile = [&](int c, int s) {
        const int k0 = c * 32;
        const uint32_t aBase = smA + s * (ASZ * 4);
        const uint32_t bBase = smA + (2 * ASZ + s * BSZ) * 4;
        if (CONV_A) {
            // A: 128 rows x 4 groups of 8 cols; 256 threads -> 2 (row,group) slots each.
            float4 va[4];
#pragma unroll
            for (int i = 0; i < 2; i++) {
                int idx = tid + i * 256;
                int row = idx >> 2, g = idx & 3;
                int m = m0 + row; if (m > M - 1) m = M - 1;
                const float4* src = (const float4*)(A + (size_t)m * K + k0 + g * 8);
                va[2 * i]     = src[0];
                va[2 * i + 1] = src[1];
            }
#pragma unroll
            for (int i = 0; i < 4; i++) {
                int idx = tid + i * 256;
                int row = idx >> 3, seg = idx & 7;
                int n = n0 + row; if (n > N - 1) n = N - 1;
                cp_async16(bBase + row * 160 + seg * 16, Bm + (size_t)n * K + k0 + seg * 4);
            }
#pragma unroll
            for (int i = 0; i < 2; i++) {
                int idx = tid + i * 256;
                int row = idx >> 2, g = idx & 3;
                float4 x = va[2 * i], y = va[2 * i + 1];
                float* dst = sm + s * ASZ + row * 40 + g * 8;
                *(float4*)dst = make_float4(round_tf32(x.x), round_tf32(y.x),
                                            round_tf32(x.y), round_tf32(y.y));
                *(float4*)(dst + 4) = make_float4(round_tf32(x.z), round_tf32(y.z),
                                                  round_tf32(x.w), round_tf32(y.w));
            }
        } else {
#pragma unroll
            for (int i = 0; i < TM / 32; i++) {
                int idx = tid + i * 256;
                int row = idx >> 3, seg = idx & 7;
                int m = m0 + row; if (m > M - 1) m = M - 1;
                cp_async16(aBase + row * 160 + seg * 16, A + (size_t)m * K + k0 + seg * 4);
            }
#pragma unroll
            for (int i = 0; i < 4; i++) {
                int idx = tid + i * 256;
                int row = idx >> 3, seg = idx & 7;
                int n = n0 + row; if (n > N - 1) n = N - 1;
                cp_async16(bBase + row * 160 + seg * 16, Bm + (size_t)n * K + k0 + seg * 4);
            }
        }
        cp_commit();
    };

    load_tile(0, 0);

    for (int c = 0; c < NKC; ++c) {
        const int s = c & 1;
        if (c + 1 < NKC) { load_tile(c + 1, s ^ 1); cp_wait<1>(); }
        else cp_wait<0>();
        __syncthreads();

        const float* As = sm + s * ASZ;
        const float* Bs = sm + 2 * ASZ + s * BSZ;
#pragma unroll
        for (int kk = 0; kk < 4; kk++) {
            uint32_t af[MT][4], bf[4][2];
#pragma unroll
            for (int mt = 0; mt < MT; mt++) {
                const float* p = As + (wm * (TM / 2) + mt * 16 + qr) * 40 + kk * 8 + 2 * qc;
                float2 v0 = *(const float2*)p;
                float2 v1 = *(const float2*)(p + 8 * 40);
                af[mt][0] = __float_as_uint(v0.x);
                af[mt][2] = __float_as_uint(v0.y);
                af[mt][1] = __float_as_uint(v1.x);
                af[mt][3] = __float_as_uint(v1.y);
            }
#pragma unroll
            for (int nt = 0; nt < 4; nt++) {
                const float* p = Bs + (wn * 32 + nt * 8 + qr) * 40 + kk * 8 + 2 * qc;
                float2 v = *(const float2*)p;
                bf[nt][0] = __float_as_uint(v.x);
                bf[nt][1] = __float_as_uint(v.y);
            }
#pragma unroll
            for (int mt = 0; mt < MT; mt++)
#pragma unroll
                for (int nt = 0; nt < 4; nt++)
                    mma_tf32(acc[mt][nt], af[mt], bf[nt]);
        }
        __syncthreads();
    }

#pragma unroll
    for (int mt = 0; mt < MT; mt++) {
#pragma unroll
        for (int nt = 0; nt < 4; nt++) {
            int rg = m0 + wm * (TM / 2) + mt * 16 + qr;
            int cg = n0 + wn * 32 + nt * 8 + qc * 2;
            if (cg >= N) continue;
#pragma unroll
            for (int h = 0; h < 2; h++) {
                int r = rg + h * 8;
                if (r >= M) continue;
                float a = acc[mt][nt][h * 2], b = acc[mt][nt][h * 2 + 1];
                if (RELU) { a = fmaxf(a, 0.f); b = fmaxf(b, 0.f); }
                if (OUT_MODE == 2) {
                    *(__half2*)(Ch + (size_t)r * N + cg) = __floats2half2_rn(a, b);
                } else if (OUT_MODE == 1) {
                    C0[(size_t)r * N + permc(cg)]     = round_tf32(a);
                    C0[(size_t)r * N + permc(cg + 1)] = round_tf32(b);
                } else {
                    *(float2*)(C0 + (size_t)r * N + cg) = make_float2(a, b);
                }
            }
        }
    }
}

// ---------------- gather + reduce ----------------
// 128 threads: cg = t&31 owns 8 cols (16B), fg = t>>5 owns an f-chunk of T1's 25 neighbors.
// fp16 HADD2 accumulation (split even/odd chains), fp32 relu per f, smem cross-fg reduce.
// NOTE: redA/redP are accessed with 128-bit LDS/STS -> MUST be 16B-aligned explicitly
// (shared float arrays only get natural 4B alignment; this caused R6/R7 traps).
__global__ __launch_bounds__(128) void gather_kernel(
    const int* __restrict__ T0, const int* __restrict__ T1, const int* __restrict__ T2)
{
    __shared__ __align__(16) float   redA[3][32][8];
    __shared__ __align__(16) __half2 redP[3][32][4];
    __shared__ const char* sP1[NF1];
    __shared__ const char* sP2[NF1 * NF2];
    const int b = blockIdx.x;
    const int t = threadIdx.x;
    const char* Rb = (const char*)g_Rh;

    if (t < NF1) sP1[t] = Rb + (size_t)T1[b * NF1 + t] * 1024;
    for (int i = t; i < NF1 * NF2; i += 128) sP2[i] = Rb + (size_t)T2[b * NF1 * NF2 + i] * 1024;
    __syncthreads();

    const int cg = t & 31, fg = t >> 5;
    const int qoff = cg * 16;
    const int poff = 512 + cg * 16;
    const int f0 = (fg == 0) ? 0 : (1 + fg * 6);
    const int f1 = 1 + (fg + 1) * 6;

    // h0 partial: sum_f P[T1_f] in half2
    __half2 pacc[4];
#pragma unroll
    for (int i = 0; i < 4; i++) pacc[i] = __floats2half2_rn(0.f, 0.f);
    for (int f = f0; f < f1; f++) {
        uint4 v = *(const uint4*)(sP1[f] + poff);
        pacc[0] = __hadd2(pacc[0], *(__half2*)&v.x);
        pacc[1] = __hadd2(pacc[1], *(__half2*)&v.y);
        pacc[2] = __hadd2(pacc[2], *(__half2*)&v.z);
        pacc[3] = __hadd2(pacc[3], *(__half2*)&v.w);
    }

    // h1 partial: sum_f relu(Q[T1_f] + 0.1 * sum_j P[T2_fj])
    float a[8];
#pragma unroll
    for (int i = 0; i < 8; i++) a[i] = 0.f;
#pragma unroll 1
    for (int f = f0; f < f1; f++) {
        uint4 qv = *(const uint4*)(sP1[f] + qoff);
        __half2 sA[4], sB[4];
#pragma unroll
        for (int i = 0; i < 4; i++) { sA[i] = __floats2half2_rn(0.f, 0.f); sB[i] = sA[i]; }
#pragma unroll
        for (int j = 0; j < NF2; j += 2) {
            uint4 u = *(const uint4*)(sP2[f * NF2 + j] + poff);
            uint4 w = *(const uint4*)(sP2[f * NF2 + j + 1] + poff);
            sA[0] = __hadd2(sA[0], *(__half2*)&u.x);
            sA[1] = __hadd2(sA[1], *(__half2*)&u.y);
            sA[2] = __hadd2(sA[2], *(__half2*)&u.z);
            sA[3] = __hadd2(sA[3], *(__half2*)&u.w);
            sB[0] = __hadd2(sB[0], *(__half2*)&w.x);
            sB[1] = __hadd2(sB[1], *(__half2*)&w.y);
            sB[2] = __hadd2(sB[2], *(__half2*)&w.z);
            sB[3] = __hadd2(sB[3], *(__half2*)&w.w);
        }
        const uint32_t* qh = (const uint32_t*)&qv;
#pragma unroll
        for (int i = 0; i < 4; i++) {
            float2 s0 = __half22float2(sA[i]);
            float2 s1 = __half22float2(sB[i]);
            float2 q  = __half22float2(*(__half2*)&qh[i]);
            float sx = s0.x + s1.x, sy = s0.y + s1.y;
            a[2 * i]     += fmaxf(fmaf(sx, 0.1f, q.x), 0.f);
            a[2 * i + 1] += fmaxf(fmaf(sy, 0.1f, q.y), 0.f);
        }
    }

    if (fg > 0) {
#pragma unroll
        for (int i = 0; i < 4; i++) redP[fg - 1][cg][i] = pacc[i];
        *(float4*)&redA[fg - 1][cg][0] = make_float4(a[0], a[1], a[2], a[3]);
        *(float4*)&redA[fg - 1][cg][4] = make_float4(a[4], a[5], a[6], a[7]);
    }
    __syncthreads();
    if (fg == 0) {
#pragma unroll
        for (int r = 0; r < 3; r++) {
#pragma unroll
            for (int i = 0; i < 4; i++) pacc[i] = __hadd2(pacc[i], redP[r][cg][i]);
            float4 x = *(const float4*)&redA[r][cg][0];
            float4 y = *(const float4*)&redA[r][cg][4];
            a[0] += x.x; a[1] += x.y; a[2] += x.z; a[3] += x.w;
            a[4] += y.x; a[5] += y.y; a[6] += y.z; a[7] += y.w;
        }
        uint4 q0v = *(const uint4*)(Rb + (size_t)T0[b] * 1024 + qoff);
        const uint32_t* qh = (const uint32_t*)&q0v;
        float h0[8], h1[8];
#pragma unroll
        for (int i = 0; i < 4; i++) {
            float2 p = __half22float2(pacc[i]);
            float2 q = __half22float2(*(__half2*)&qh[i]);
            h0[2 * i]     = fmaxf(fmaf(p.x, 1.f / 25.f, q.x), 0.f);
            h0[2 * i + 1] = fmaxf(fmaf(p.y, 1.f / 25.f, q.y), 0.f);
            h1[2 * i]     = a[2 * i] * (1.f / 25.f);
            h1[2 * i + 1] = a[2 * i + 1] * (1.f / 25.f);
        }
        // permuted group store: dst[0..7] = src[0,4,1,5,2,6,3,7]
        float* Cr = g_C + b * 512 + cg * 8;
        *(float4*)Cr = make_float4(round_tf32(h0[0]), round_tf32(h0[4]),
                                   round_tf32(h0[1]), round_tf32(h0[5]));
        *(float4*)(Cr + 4) = make_float4(round_tf32(h0[2]), round_tf32(h0[6]),
                                         round_tf32(h0[3]), round_tf32(h0[7]));
        *(float4*)(Cr + 256) = make_float4(round_tf32(h1[0]), round_tf32(h1[4]),
                                           round_tf32(h1[1]), round_tf32(h1[5]));
        *(float4*)(Cr + 260) = make_float4(round_tf32(h1[2]), round_tf32(h1[6]),
                                           round_tf32(h1[3]), round_tf32(h1[7]));
    }
}

// ---------------- launch ----------------
static constexpr int SM128 = 2 * (128 * 40 + 128 * 40) * 4;  // 81920
static constexpr int SM64  = 2 * (64 * 40 + 128 * 40) * 4;   // 61440

extern "C" void kernel_launch(void* const* d_in, const int* in_sizes, int n_in,
                              void* d_out, int out_size)
{
    const int* T0 = (const int*)d_in[0];
    const int* T1 = (const int*)d_in[1];
    const int* T2 = (const int*)d_in[2];
    const float* emb = (const float*)d_in[3];
    const float* W1 = (const float*)d_in[4];
    const float* W2 = (const float*)d_in[5];
    const float* W3 = (const float*)d_in[6];
    float* out = (float*)d_out;

    void *pRh, *pW, *pW2, *pW3, *pC, *pE;
    cudaGetSymbolAddress(&pRh, g_Rh);
    cudaGetSymbolAddress(&pW, g_Wcat);
    cudaGetSymbolAddress(&pW2, g_W2r);
    cudaGetSymbolAddress(&pW3, g_W3r);
    cudaGetSymbolAddress(&pC, g_C);
    cudaGetSymbolAddress(&pE, g_E);

    cudaFuncSetAttribute((const void*)tf32_gemm<128, false, 2, true>,
                         cudaFuncAttributeMaxDynamicSharedMemorySize, SM128);
    cudaFuncSetAttribute((const void*)tf32_gemm<64, true, 1, false>,
                         cudaFuncAttributeMaxDynamicSharedMemorySize, SM64);
    cudaFuncSetAttribute((const void*)tf32_gemm<64, false, 0, false>,
                         cudaFuncAttributeMaxDynamicSharedMemorySize, SM64);

    // 1) round+permute weights
    conv_w<<<1088, 256>>>(W1, W2, W3);

    // 2) R = emb @ Wcat^T : [100000, 512] -> g_Rh fp16 (A rounded+permuted in-loader)
    {
        dim3 grid(4, (NODES + 127) / 128);
        tf32_gemm<128, false, 2, true><<<grid, 256, SM128>>>(
            emb, (const float*)pW, nullptr, (__half*)pRh, NODES, 512, 256);
    }

    // 3) gather + reduce -> g_C [4096, 512] (rounded, K-permuted)
    gather_kernel<<<BATCH, 128>>>(T0, T1, T2);

    // 4) E = relu(C @ W2^T) : [4096, 256], K=512 -> g_E (rounded, K-permuted)
    {
        dim3 grid(2, BATCH / 64);
        tf32_gemm<64, true, 1, false><<<grid, 256, SM64>>>(
            (const float*)pC, (const float*)pW2, (float*)pE, nullptr, BATCH, 256, 512);
    }

    // 5) scores = E @ W3^T : [4096, 64], K=256 -> out fp32
    {
        dim3 grid(1, BATCH / 64);
        tf32_gemm<64, false, 0, false><<<grid, 256, SM64>>>(
            (const float*)pE, (const float*)pW3, out, nullptr, BATCH, 64, 256);
    }
}